// round 4
// baseline (speedup 1.0000x reference)
#include <cuda_runtime.h>

// ---------------- problem constants ----------------
#define B_    64
#define T_    24
#define N_    300
#define F_    16
#define D_    64     // D1 == D2
#define C_    128    // C1 == C2
#define H_    12
#define BT_   (B_ * T_)        // 1536
#define BTN_  (BT_ * N_)       // 460800
#define ND_   (N_ * D_)        // 19200
#define MLPIN_ (ND_ + C_)      // 19328
#define KCONV_ (3 * ND_)       // 57600

#define CONV_SK   12           // split-K factor for conv1 (57600/12 = 4800, within one k-shift)
#define CONV_KCH  4800
#define MLP1_SK   8            // split-K for MLP1 (19328/8 = 2416, divisible by 16)
#define MLP1_KCH  2416

// ---------------- scratch (device globals; no allocation) ----------------
__device__ float g_S[BTN_ * D_];                    // support buffer  (118 MB)
__device__ float g_Hh[BTN_ * D_];                   // hidden buffer   (118 MB)
__device__ float g_w1p[KCONV_ * C_];                // repacked conv_w1 (k,cin,c)
__device__ float g_y1part[CONV_SK * B_ * C_ * T_];  // conv1 split-K partials
__device__ float g_pooled[B_ * C_];                 // temporal pooled
__device__ float g_z1part[MLP1_SK * B_ * 512];      // mlp1 split-K partials
__device__ float g_z2[B_ * 256];                    // mlp2 out

// ---------------- K0: repack conv_w1 (c,cin,k) -> (k,cin,c) ----------------
__global__ void k_repack(const float* __restrict__ w1)
{
    __shared__ float s[32][97];
    const int cin0 = blockIdx.x * 32;
    const int c0   = blockIdx.y * 32;
    const int tid  = threadIdx.x;
    // load 32 c-rows x 96 (cin*3+k) contiguous floats, coalesced
    for (int i = tid; i < 32 * 96; i += 256) {
        int cl = i / 96, j = i - cl * 96;
        s[cl][j] = w1[(c0 + cl) * 57600 + cin0 * 3 + j];
    }
    __syncthreads();
    // write (k,cin,c) with c contiguous -> coalesced
    for (int i = tid; i < 3 * 32 * 32; i += 256) {
        int cl  = i & 31;
        int cil = (i >> 5) & 31;
        int k   = i >> 10;
        g_w1p[(k * ND_ + cin0 + cil) * C_ + c0 + cl] = s[cl][cil * 3 + k];
    }
}

// ---------------- K1: support1 = x @ gcn_w1   (460800 x 16 x 64) ----------------
__global__ void k_xw1(const float* __restrict__ x, const float* __restrict__ w)
{
    __shared__ float ws[16 * 64];
    __shared__ float xs[64 * 16];
    const int tid  = threadIdx.x;
    const int row0 = blockIdx.x * 64;
    for (int i = tid; i < 1024; i += 256) ws[i] = w[i];
    for (int i = tid; i < 1024; i += 256) xs[i] = x[row0 * 16 + i];
    __syncthreads();
    for (int i = tid; i < 4096; i += 256) {
        int r = i >> 6, d = i & 63;
        float acc = 0.f;
        #pragma unroll
        for (int k = 0; k < 16; k++) acc = fmaf(xs[r * 16 + k], ws[k * 64 + d], acc);
        g_S[(row0 + r) * 64 + d] = acc;
    }
}

// ---------------- K2: h = relu(adj @ S + bias)  batched over bt ----------------
// reads g_S, writes g_Hh. grid = (5 m-tiles, 1536 bt)
__global__ void k_adj(const float* __restrict__ adj, const float* __restrict__ bias)
{
    const int bt = blockIdx.y;
    const int m0 = blockIdx.x * 64;
    const float* Sb = g_S + (size_t)bt * ND_;
    __shared__ float Ast[16][68];   // [k][m]
    __shared__ float Bs[16][68];    // [k][d]
    const int tid = threadIdx.x;
    const int tx = tid & 15, ty = tid >> 4;
    float acc[4][4] = {};
    for (int k0 = 0; k0 < N_; k0 += 16) {
        for (int i = tid; i < 1024; i += 256) {
            int r = i >> 4, k = i & 15;
            int m = m0 + r, kk = k0 + k;
            Ast[k][r] = (m < N_ && kk < N_) ? adj[m * N_ + kk] : 0.f;
        }
        for (int i = tid; i < 1024; i += 256) {
            int k = i >> 6, d = i & 63;
            int kk = k0 + k;
            Bs[k][d] = (kk < N_) ? Sb[kk * D_ + d] : 0.f;
        }
        __syncthreads();
        #pragma unroll
        for (int k = 0; k < 16; k++) {
            float4 a4 = *reinterpret_cast<const float4*>(&Ast[k][ty * 4]);
            float4 b4 = *reinterpret_cast<const float4*>(&Bs[k][tx * 4]);
            float a[4] = {a4.x, a4.y, a4.z, a4.w};
            float b[4] = {b4.x, b4.y, b4.z, b4.w};
            #pragma unroll
            for (int i = 0; i < 4; i++)
                #pragma unroll
                for (int j = 0; j < 4; j++) acc[i][j] = fmaf(a[i], b[j], acc[i][j]);
        }
        __syncthreads();
    }
    #pragma unroll
    for (int i = 0; i < 4; i++) {
        int m = m0 + ty * 4 + i;
        if (m < N_) {
            #pragma unroll
            for (int j = 0; j < 4; j++) {
                int d = tx * 4 + j;
                g_Hh[((size_t)bt * N_ + m) * D_ + d] = fmaxf(acc[i][j] + bias[d], 0.f);
            }
        }
    }
}

// ---------------- K3: support2 = h1 @ gcn_w2   (460800 x 64 x 64) ----------------
// reads g_Hh, writes g_S
__global__ void k_hw2(const float* __restrict__ w)
{
    const int r0 = blockIdx.x * 64;
    __shared__ float Ast[16][68];
    __shared__ float Bs[16][68];
    const int tid = threadIdx.x;
    const int tx = tid & 15, ty = tid >> 4;
    float acc[4][4] = {};
    for (int k0 = 0; k0 < D_; k0 += 16) {
        for (int i = tid; i < 1024; i += 256) {
            int r = i >> 4, k = i & 15;
            Ast[k][r] = g_Hh[(size_t)(r0 + r) * D_ + k0 + k];
        }
        for (int i = tid; i < 1024; i += 256) {
            int k = i >> 6, d = i & 63;
            Bs[k][d] = w[(k0 + k) * D_ + d];
        }
        __syncthreads();
        #pragma unroll
        for (int k = 0; k < 16; k++) {
            float4 a4 = *reinterpret_cast<const float4*>(&Ast[k][ty * 4]);
            float4 b4 = *reinterpret_cast<const float4*>(&Bs[k][tx * 4]);
            float a[4] = {a4.x, a4.y, a4.z, a4.w};
            float b[4] = {b4.x, b4.y, b4.z, b4.w};
            #pragma unroll
            for (int i = 0; i < 4; i++)
                #pragma unroll
                for (int j = 0; j < 4; j++) acc[i][j] = fmaf(a[i], b[j], acc[i][j]);
        }
        __syncthreads();
    }
    #pragma unroll
    for (int i = 0; i < 4; i++)
        #pragma unroll
        for (int j = 0; j < 4; j++)
            g_S[(size_t)(r0 + ty * 4 + i) * D_ + tx * 4 + j] = acc[i][j];
}

// ---------------- K4: conv1 as split-K GEMM, partials out ----------------
// y1part[ks][b][c][t] = sum over K-chunk of w1p[kg][c] * H[b, t+kshift-1, cin]
// grid = (48 bt-tiles, CONV_SK)
__global__ void k_conv1()
{
    const int bt0 = blockIdx.x * 32;
    const int kb0 = blockIdx.y * CONV_KCH;
    const int kshift = kb0 / ND_;
    const int cin0 = kb0 - kshift * ND_;
    __shared__ float Ast[32][36];    // [k][row]
    __shared__ float Bs[32][132];    // [k][c]
    __shared__ int rowOff[32];
    const int tid = threadIdx.x;
    if (tid < 32) {
        int bt = bt0 + tid;
        int b = bt / T_, t = bt - b * T_;
        int tp = t + kshift - 1;
        rowOff[tid] = (tp >= 0 && tp < T_) ? (b * T_ + tp) * ND_ : -1;
    }
    __syncthreads();
    const int tx = tid & 31, ty = tid >> 5;   // 32 col-groups x 8 row-groups
    float acc[4][4] = {};
    for (int c0 = 0; c0 < CONV_KCH; c0 += 32) {
        for (int i = tid; i < 1024; i += 256) {
            int r = i >> 5, k = i & 31;
            int off = rowOff[r];
            Ast[k][r] = (off >= 0) ? g_Hh[off + cin0 + c0 + k] : 0.f;
        }
        for (int i = tid; i < 4096; i += 256) {
            int k = i >> 7, c = i & 127;
            Bs[k][c] = g_w1p[(kb0 + c0 + k) * C_ + c];
        }
        __syncthreads();
        #pragma unroll
        for (int k = 0; k < 32; k++) {
            float4 a4 = *reinterpret_cast<const float4*>(&Ast[k][ty * 4]);
            float4 b4 = *reinterpret_cast<const float4*>(&Bs[k][tx * 4]);
            float a[4] = {a4.x, a4.y, a4.z, a4.w};
            float b[4] = {b4.x, b4.y, b4.z, b4.w};
            #pragma unroll
            for (int i = 0; i < 4; i++)
                #pragma unroll
                for (int j = 0; j < 4; j++) acc[i][j] = fmaf(a[i], b[j], acc[i][j]);
        }
        __syncthreads();
    }
    const int ks = blockIdx.y;
    #pragma unroll
    for (int i = 0; i < 4; i++) {
        int bt = bt0 + ty * 4 + i;
        int b = bt / T_, t = bt - b * T_;
        #pragma unroll
        for (int j = 0; j < 4; j++) {
            int c = tx * 4 + j;
            g_y1part[((ks * B_ + b) * C_ + c) * T_ + t] = acc[i][j];
        }
    }
}

// ---------------- K5: conv2 + relu + temporal mean-pool ----------------
// one block per batch b. Static smem only (padded y1 tile, 13.3 KB).
// conv_w2 (196 KB) is read straight from global: it fits L2 and is reused by
// all 64 blocks; load:FMA ratio is 1:6 so latency hides under ILP.
__global__ void k_conv2pool(const float* __restrict__ cb1,
                            const float* __restrict__ w2,
                            const float* __restrict__ cb2)
{
    __shared__ float ys[C_ * 26];     // [c1][26] padded t (slots 0 and 25 zero)
    const int b = blockIdx.x;
    const int tid = threadIdx.x;
    // y1 = relu(sum of split-K partials + conv_b1), into padded smem
    for (int i = tid; i < C_ * T_; i += 256) {
        int c = i / T_, t = i - c * T_;
        float v = cb1[c];
        #pragma unroll
        for (int s = 0; s < CONV_SK; s++)
            v += g_y1part[((s * B_ + b) * C_ + c) * T_ + t];
        ys[c * 26 + t + 1] = fmaxf(v, 0.f);
    }
    if (tid < C_) { ys[tid * 26 + 0] = 0.f; ys[tid * 26 + 25] = 0.f; }
    __syncthreads();

    const int c = tid >> 1;           // output channel (two threads per c)
    const int half = tid & 1;
    const int tbase = half * 12;
    const float bias2 = cb2[c];
    const float* wrow = w2 + c * (C_ * 3);   // (c, c1, k) layout: 384 floats
    float acc[12];
    #pragma unroll
    for (int tt = 0; tt < 12; tt++) acc[tt] = bias2;
    for (int c1 = 0; c1 < C_; c1++) {
        float w0 = wrow[c1 * 3 + 0];
        float w1 = wrow[c1 * 3 + 1];
        float w2v = wrow[c1 * 3 + 2];
        float yv[14];
        #pragma unroll
        for (int idx = 0; idx < 14; idx++) yv[idx] = ys[c1 * 26 + tbase + idx];
        #pragma unroll
        for (int tt = 0; tt < 12; tt++)
            acc[tt] += w0 * yv[tt] + w1 * yv[tt + 1] + w2v * yv[tt + 2];
    }
    float s = 0.f;
    #pragma unroll
    for (int tt = 0; tt < 12; tt++) s += fmaxf(acc[tt], 0.f);
    s += __shfl_xor_sync(0xffffffffu, s, 1);
    if (half == 0) g_pooled[b * C_ + c] = s * (1.f / 24.f);
}

// ---------------- K6: MLP1 split-K, partials out (64 x 19328 x 512) ----------------
// combined row b = [ g_Hh[b, T-1, :] (19200) | pooled[b] (128) ]
// grid = (8 n-tiles, MLP1_SK)
__global__ void k_mlp1(const float* __restrict__ w)
{
    const int n0  = blockIdx.x * 64;
    const int kc0 = blockIdx.y * MLP1_KCH;
    __shared__ float Ast[16][68];
    __shared__ float Bs[16][68];
    const int tid = threadIdx.x;
    const int tx = tid & 15, ty = tid >> 4;
    float acc[4][4] = {};
    for (int k0 = 0; k0 < MLP1_KCH; k0 += 16) {
        for (int i = tid; i < 1024; i += 256) {
            int r = i >> 4, k = i & 15;
            int kg = kc0 + k0 + k;
            float v;
            if (kg < ND_) v = g_Hh[(r * T_ + (T_ - 1)) * ND_ + kg];
            else          v = g_pooled[r * C_ + (kg - ND_)];
            Ast[k][r] = v;
        }
        for (int i = tid; i < 1024; i += 256) {
            int k = i >> 6, d = i & 63;
            Bs[k][d] = w[(kc0 + k0 + k) * 512 + n0 + d];
        }
        __syncthreads();
        #pragma unroll
        for (int k = 0; k < 16; k++) {
            float4 a4 = *reinterpret_cast<const float4*>(&Ast[k][ty * 4]);
            float4 b4 = *reinterpret_cast<const float4*>(&Bs[k][tx * 4]);
            float a[4] = {a4.x, a4.y, a4.z, a4.w};
            float b[4] = {b4.x, b4.y, b4.z, b4.w};
            #pragma unroll
            for (int i = 0; i < 4; i++)
                #pragma unroll
                for (int j = 0; j < 4; j++) acc[i][j] = fmaf(a[i], b[j], acc[i][j]);
        }
        __syncthreads();
    }
    const int ks = blockIdx.y;
    #pragma unroll
    for (int i = 0; i < 4; i++)
        #pragma unroll
        for (int j = 0; j < 4; j++)
            g_z1part[(ks * B_ + ty * 4 + i) * 512 + n0 + tx * 4 + j] = acc[i][j];
}

// ---------------- K7: MLP2  z2 = relu(relu(z1)@w2 + b2)  (64 x 512 x 256) ----------
__global__ void k_mlp2(const float* __restrict__ mb1, const float* __restrict__ w,
                       const float* __restrict__ mb2)
{
    const int n0 = blockIdx.x * 64;
    __shared__ float Ast[16][68];
    __shared__ float Bs[16][68];
    const int tid = threadIdx.x;
    const int tx = tid & 15, ty = tid >> 4;
    float acc[4][4] = {};
    for (int k0 = 0; k0 < 512; k0 += 16) {
        for (int i = tid; i < 1024; i += 256) {
            int r = i >> 4, k = i & 15;
            int kg = k0 + k;
            float v = mb1[kg];
            #pragma unroll
            for (int s = 0; s < MLP1_SK; s++) v += g_z1part[(s * B_ + r) * 512 + kg];
            Ast[k][r] = fmaxf(v, 0.f);
        }
        for (int i = tid; i < 1024; i += 256) {
            int k = i >> 6, d = i & 63;
            Bs[k][d] = w[(k0 + k) * 256 + n0 + d];
        }
        __syncthreads();
        #pragma unroll
        for (int k = 0; k < 16; k++) {
            float4 a4 = *reinterpret_cast<const float4*>(&Ast[k][ty * 4]);
            float4 b4 = *reinterpret_cast<const float4*>(&Bs[k][tx * 4]);
            float a[4] = {a4.x, a4.y, a4.z, a4.w};
            float b[4] = {b4.x, b4.y, b4.z, b4.w};
            #pragma unroll
            for (int i = 0; i < 4; i++)
                #pragma unroll
                for (int j = 0; j < 4; j++) acc[i][j] = fmaf(a[i], b[j], acc[i][j]);
        }
        __syncthreads();
    }
    #pragma unroll
    for (int i = 0; i < 4; i++)
        #pragma unroll
        for (int j = 0; j < 4; j++) {
            int n = n0 + tx * 4 + j;
            g_z2[(ty * 4 + i) * 256 + n] = fmaxf(acc[i][j] + mb2[n], 0.f);
        }
}

// ---------------- K8: MLP3  preds = z2@w3 + b3  (64 x 256 x 3600) -> d_out -----------
__global__ void k_mlp3(const float* __restrict__ w, const float* __restrict__ mb3,
                       float* __restrict__ out)
{
    const int n0 = blockIdx.x * 64;
    __shared__ float Ast[16][68];
    __shared__ float Bs[16][68];
    const int tid = threadIdx.x;
    const int tx = tid & 15, ty = tid >> 4;
    float acc[4][4] = {};
    for (int k0 = 0; k0 < 256; k0 += 16) {
        for (int i = tid; i < 1024; i += 256) {
            int r = i >> 4, k = i & 15;
            Ast[k][r] = g_z2[r * 256 + k0 + k];
        }
        for (int i = tid; i < 1024; i += 256) {
            int k = i >> 6, d = i & 63;
            int n = n0 + d;
            Bs[k][d] = (n < N_ * H_) ? w[(k0 + k) * (N_ * H_) + n] : 0.f;
        }
        __syncthreads();
        #pragma unroll
        for (int k = 0; k < 16; k++) {
            float4 a4 = *reinterpret_cast<const float4*>(&Ast[k][ty * 4]);
            float4 b4 = *reinterpret_cast<const float4*>(&Bs[k][tx * 4]);
            float a[4] = {a4.x, a4.y, a4.z, a4.w};
            float b[4] = {b4.x, b4.y, b4.z, b4.w};
            #pragma unroll
            for (int i = 0; i < 4; i++)
                #pragma unroll
                for (int j = 0; j < 4; j++) acc[i][j] = fmaf(a[i], b[j], acc[i][j]);
        }
        __syncthreads();
    }
    #pragma unroll
    for (int i = 0; i < 4; i++)
        #pragma unroll
        for (int j = 0; j < 4; j++) {
            int n = n0 + tx * 4 + j;
            if (n < N_ * H_)
                out[(ty * 4 + i) * (N_ * H_) + n] = acc[i][j] + mb3[n];
        }
}

// ---------------- launch ----------------
extern "C" void kernel_launch(void* const* d_in, const int* in_sizes, int n_in,
                              void* d_out, int out_size)
{
    const float* x    = (const float*)d_in[0];
    const float* adj  = (const float*)d_in[1];
    const float* gw1  = (const float*)d_in[2];
    const float* gb1  = (const float*)d_in[3];
    const float* gw2  = (const float*)d_in[4];
    const float* gb2  = (const float*)d_in[5];
    const float* cw1  = (const float*)d_in[6];
    const float* cb1  = (const float*)d_in[7];
    const float* cw2  = (const float*)d_in[8];
    const float* cb2  = (const float*)d_in[9];
    const float* mw1  = (const float*)d_in[10];
    const float* mb1  = (const float*)d_in[11];
    const float* mw2  = (const float*)d_in[12];
    const float* mb2  = (const float*)d_in[13];
    const float* mw3  = (const float*)d_in[14];
    const float* mb3  = (const float*)d_in[15];
    float* out = (float*)d_out;

    k_repack<<<dim3(ND_ / 32, C_ / 32), 256>>>(cw1);
    k_xw1<<<BTN_ / 64, 256>>>(x, gw1);
    k_adj<<<dim3(5, BT_), 256>>>(adj, gb1);          // h1 = relu(adj@S1 + b1)
    k_hw2<<<BTN_ / 64, 256>>>(gw2);                  // S2 = h1 @ W2
    k_adj<<<dim3(5, BT_), 256>>>(adj, gb2);          // h2 = relu(adj@S2 + b2)
    k_conv1<<<dim3(BT_ / 32, CONV_SK), 256>>>();
    k_conv2pool<<<B_, 256>>>(cb1, cw2, cb2);
    k_mlp1<<<dim3(512 / 64, MLP1_SK), 256>>>(mw1);
    k_mlp2<<<256 / 64, 256>>>(mb1, mw2, mb2);
    k_mlp3<<<(N_ * H_ + 63) / 64, 256>>>(mw3, mb3, out);
}